// round 10
// baseline (speedup 1.0000x reference)
#include <cuda_runtime.h>

// Problem constants
#define IN_F    2048
#define OUT_F   4096
#define BATCHN  131072
#define IN_F4   (IN_F / 4)        // 512 float4 columns

#define NTHREADS 512              // 16 warps per block

// Fused-kernel block layout (producer bids < consumer bids; low bids are
// wave-1 resident deterministically => deadlock-free spins).
#define NFOLD    16               // folder blocks (bids 0..15)
#define BID_BIAS 16
#define NRED     256              // weight reducers (bids 17..272), 16 rows x 512 cols
#define BID_RED0 17
#define BID_GEMV0 (BID_RED0 + NRED)          // 273
#define NGEMV    (BATCHN / 16)               // 8192 (16 rows per block)
#define GRID_TOTAL (BID_GEMV0 + NGEMV)       // 8465

#define NSLICE   256              // 4096 rows / 16 rows per reducer slice

// Scratch globals (allocation-free, fully rewritten every launch =>
// graph-replay deterministic).
__device__ float4 g_partial4[NSLICE * IN_F4];   // 2 MiB
__device__ float  g_wsum[IN_F];
__device__ float  g_bsum;
__device__ int    g_red_done;     // -> NRED
__device__ int    g_fold_done;    // -> NFOLD + 1

__global__ void init_kernel() {
    g_red_done  = 0;
    g_fold_done = 0;
}

// ---------------------------------------------------------------------------
__global__ __launch_bounds__(NTHREADS) void fused_kernel(const float4* __restrict__ w4,
                                                         const float*  __restrict__ x,
                                                         const float*  __restrict__ bias,
                                                         float* __restrict__ out) {
    __shared__ float4 sw[IN_F4];      // 8 KB
    const int tid = threadIdx.x;
    const int bid = blockIdx.x;

    // ======================== GEMV blocks (hot path) ========================
    if (bid >= BID_GEMV0) {
        const int gvb  = bid - BID_GEMV0;
        const int warp = tid >> 5;
        const int lane = tid & 31;
        const int row  = gvb * 16 + warp;
        const float4* xr = reinterpret_cast<const float4*>(x + (size_t)row * IN_F);

        // Issue first half of this thread's REAL x loads before waiting.
        // Register-destined, single-use: overlaps the weight reduction
        // without polluting L2.
        float4 xa[8];
        #pragma unroll
        for (int i = 0; i < 8; ++i) {
            xa[i] = xr[i * 32 + lane];
        }

        // Wait for w_sum + b_sum (loads above stay in flight).
        if (tid == 0) {
            int backoff = 32;
            while (*(volatile int*)&g_fold_done != (NFOLD + 1)) {
                __nanosleep(backoff);
                if (backoff < 1024) backoff <<= 1;
            }
            __threadfence();
        }
        __syncthreads();

        // Stage w_sum into shared (512 threads -> one pass).
        sw[tid] = reinterpret_cast<const float4*>(g_wsum)[tid];
        __syncthreads();
        const float bsum = g_bsum;

        float acc = 0.0f;
        #pragma unroll
        for (int i = 0; i < 8; ++i) {           // preloaded half
            const float4 wv = sw[i * 32 + lane];
            acc += xa[i].x * wv.x + xa[i].y * wv.y + xa[i].z * wv.z + xa[i].w * wv.w;
        }
        #pragma unroll
        for (int i = 8; i < 16; ++i) {          // streamed half
            const float4 xv = xr[i * 32 + lane];
            const float4 wv = sw[i * 32 + lane];
            acc += xv.x * wv.x + xv.y * wv.y + xv.z * wv.z + xv.w * wv.w;
        }
        #pragma unroll
        for (int off = 16; off > 0; off >>= 1) {
            acc += __shfl_xor_sync(0xFFFFFFFFu, acc, off);
        }
        if (lane == 0) out[row] = acc + bsum;
        return;
    }

    // ======================== Weight reducer blocks ========================
    if (bid >= BID_RED0) {
        const int s = bid - BID_RED0;          // 16-row slice, all 512 f4-cols
        const float4* wp = w4 + (size_t)(s * 16) * IN_F4 + tid;

        float4 acc = make_float4(0.f, 0.f, 0.f, 0.f);
        #pragma unroll
        for (int b = 0; b < 2; ++b) {
            float4 t[8];
            #pragma unroll
            for (int i = 0; i < 8; ++i) t[i] = wp[(size_t)(b * 8 + i) * IN_F4];
            #pragma unroll
            for (int i = 0; i < 8; ++i) {
                acc.x += t[i].x; acc.y += t[i].y; acc.z += t[i].z; acc.w += t[i].w;
            }
        }
        g_partial4[s * IN_F4 + tid] = acc;
        __threadfence();
        __syncthreads();
        if (tid == 0) atomicAdd(&g_red_done, 1);
        return;
    }

    // ======================== Bias block ========================
    if (bid == BID_BIAS) {
        __shared__ float red[NTHREADS];
        float s = 0.0f;
        #pragma unroll
        for (int i = 0; i < OUT_F / NTHREADS; ++i) s += bias[i * NTHREADS + tid];
        red[tid] = s;
        __syncthreads();
        #pragma unroll
        for (int stride = NTHREADS / 2; stride > 0; stride >>= 1) {
            if (tid < stride) red[tid] += red[tid + stride];
            __syncthreads();
        }
        if (tid == 0) {
            g_bsum = red[0];
            __threadfence();
            atomicAdd(&g_fold_done, 1);
        }
        return;
    }

    // ======================== Folder blocks (bids 0..15) ========================
    {
        if (tid == 0) {
            int backoff = 32;
            while (*(volatile int*)&g_red_done != NRED) {
                __nanosleep(backoff);
                if (backoff < 1024) backoff <<= 1;
            }
            __threadfence();
        }
        __syncthreads();

        const int lane = tid & 31;
        const int wrp  = tid >> 5;           // 16 warps = 16 slice groups
        const int col  = bid * 32 + lane;    // this block's 32 float4 columns

        // Each warp folds 16 of the 256 slices (p = wrp + 16*j).
        float4 acc = make_float4(0.f, 0.f, 0.f, 0.f);
        #pragma unroll
        for (int j = 0; j < 16; ++j) {
            const float4 v = g_partial4[(wrp + 16 * j) * IN_F4 + col];
            acc.x += v.x; acc.y += v.y; acc.z += v.z; acc.w += v.w;
        }

        float4* sh = sw;                     // 16*32 float4 = 8 KB
        sh[wrp * 32 + lane] = acc;
        __syncthreads();
        if (wrp == 0) {
            float4 t = sh[lane];
            #pragma unroll
            for (int p = 1; p < 16; ++p) {
                const float4 v = sh[p * 32 + lane];
                t.x += v.x; t.y += v.y; t.z += v.z; t.w += v.w;
            }
            reinterpret_cast<float4*>(g_wsum)[col] = t;
            __threadfence();
        }
        __syncthreads();
        if (tid == 0) atomicAdd(&g_fold_done, 1);
        return;
    }
}

// ---------------------------------------------------------------------------
extern "C" void kernel_launch(void* const* d_in, const int* in_sizes, int n_in,
                              void* d_out, int out_size) {
    const float* x      = (const float*)d_in[0];  // (131072, 2048)
    const float* weight = (const float*)d_in[1];  // (4096, 2048)
    const float* bias   = (const float*)d_in[2];  // (4096,)
    float* out = (float*)d_out;                   // (131072, 1)

    (void)in_sizes; (void)n_in; (void)out_size;

    init_kernel<<<1, 1>>>();
    fused_kernel<<<GRID_TOTAL, NTHREADS>>>(reinterpret_cast<const float4*>(weight),
                                           x, bias, out);
}